// round 16
// baseline (speedup 1.0000x reference)
#include <cuda_runtime.h>
#include <cstdint>

// out[b,t,:] = ((vf[b] @ Wv + bv) @ Wp + bp), broadcast over t.
// (keys/values broadcast over T -> softmax uniform -> y == v; x/Wq/Wk drop out)
//
// Single fused persistent kernel, 256 blocks x 512 threads (2 CTAs/SM,
// 32 warps/SM). work item = (slab of 128 cols, k-chunk of 32 rows): 8 x 32.
//   Phase A: g_p1[kc][b][c] = sum_{k in chunk} vf[b,k] * Wv[k,c]
//   [prefetch Wp tile]  barrier0 (release/acquire, monotonic counter)
//   Phase B: stage vv = fold32(g_p1)+bv (4-way parallel), then @ Wp-tile
//   [prefetch bp]       barrier1
//   Phase C: r = fold32(g_p2)+bp (2-way parallel); TMA bulk broadcast 16 rows
// All float reductions fixed-order (deterministic).
// Static smem ~46.5 KB (< 48 KB limit); 2 CTAs/SM -> 93 KB/SM, capacity 296>=256.

#define C_     1024
#define B_     4
#define T_     1024
#define GRID_  256
#define BLOCK_ 512
#define NKC_   32     // k-chunks
#define KCH_   32     // rows per k-chunk
#define NSLAB_ 8      // column slabs
#define SLABW_ 128    // columns per slab

__device__ float g_p1[NKC_][B_][C_];   // 512 KB, L2-resident
__device__ float g_p2[NKC_][B_][C_];   // 512 KB
__device__ unsigned g_barcnt[2];       // monotonic across graph replays

__device__ __forceinline__ void grid_barrier(int i) {
    __syncthreads();
    if (threadIdx.x == 0) {
        unsigned* ctr = &g_barcnt[i];
        unsigned old;
        asm volatile("atom.release.gpu.global.add.u32 %0, [%1], 1;"
                     : "=r"(old) : "l"(ctr) : "memory");
        const unsigned target = (old / GRID_ + 1u) * GRID_;
        unsigned cur;
        do {
            asm volatile("ld.acquire.gpu.global.u32 %0, [%1];"
                         : "=r"(cur) : "l"(ctr) : "memory");
        } while ((int)(cur - target) < 0);
    }
    __syncthreads();
}

struct WTile { float4 w0, w1; };

// 16 warps: warp w owns rows k0+2w, k0+2w+1 (2 independent LDG.128/thread).
__device__ __forceinline__ WTile load_wtile(const float* __restrict__ W,
                                            int k0, int slab, int tid) {
    const int lane = tid & 31;
    const int w    = tid >> 5;
    const float* wp = &W[(size_t)(k0 + w * 2) * C_ + slab * SLABW_ + lane * 4];
    WTile t;
    t.w0 = *(const float4*)(wp);
    t.w1 = *(const float4*)(wp + C_);
    return t;
}

// Rank-2 update per warp + fixed-order 16-warp in-block k reduce.
__device__ __forceinline__ void gemv_compute(
    const WTile& t,
    const float (&s_in)[B_][KCH_],
    float (&s_red)[16][B_][SLABW_],
    int slab, int tid,
    float* __restrict__ gout)          // g_pX[kc] : [B_][C_] flat
{
    const int lane = tid & 31;
    const int w    = tid >> 5;
    const int kw   = w * 2;

#pragma unroll
    for (int b = 0; b < B_; b++) {
        const float a0 = s_in[b][kw + 0];
        const float a1 = s_in[b][kw + 1];
        float4 acc;
        acc.x = a0 * t.w0.x + a1 * t.w1.x;
        acc.y = a0 * t.w0.y + a1 * t.w1.y;
        acc.z = a0 * t.w0.z + a1 * t.w1.z;
        acc.w = a0 * t.w0.w + a1 * t.w1.w;
        *(float4*)&s_red[w][b][lane * 4] = acc;
    }
    __syncthreads();

    const int rb = tid >> 7;           // 0..3
    const int rc = tid & 127;
    float s = 0.f;
#pragma unroll
    for (int ww = 0; ww < 16; ww++) s += s_red[ww][rb][rc];
    gout[rb * C_ + slab * SLABW_ + rc] = s;
}

__global__ void __launch_bounds__(BLOCK_, 2) ca_fused(
    const float* __restrict__ vf, const float* __restrict__ Wv,
    const float* __restrict__ bv, const float* __restrict__ Wp,
    const float* __restrict__ bp, float* __restrict__ out)
{
    __shared__ __align__(16) float  s_in[B_][KCH_];           // 0.5 KB
    __shared__ __align__(16) float  s_red[16][B_][SLABW_];    // 32 KB
    __shared__ __align__(16) float  s_row[C_];                // 4 KB
    __shared__ __align__(16) float4 s_fold[BLOCK_];           // 8 KB
    __shared__ float                s_pf[B_ * KCH_][4];       // 2 KB

    const int bid  = blockIdx.x;
    const int tid  = threadIdx.x;
    const int slab = bid & (NSLAB_ - 1);
    const int kc   = bid >> 3;          // 0..31
    const int k0   = kc * KCH_;

    // ---- Phase A: g_p1[kc] = vf-chunk @ Wv-tile ----
    const WTile tv = load_wtile(Wv, k0, slab, tid);
    if (tid < B_ * KCH_) {
        const int b = tid >> 5, j = tid & 31;
        s_in[b][j] = vf[b * C_ + k0 + j];
    }
    __syncthreads();
    gemv_compute(tv, s_in, s_red, slab, tid, &g_p1[kc][0][0]);

    // Prefetch Wp tile BEFORE the barrier (latency hidden by the wait).
    const WTile tp = load_wtile(Wp, k0, slab, tid);
    grid_barrier(0);

    // ---- Phase B: stage vv chunk (fold 32 partials + bv, 4-way parallel) ----
    {
        const int pair = tid >> 2;      // 0..127 = (b, j)
        const int sub  = tid & 3;
        const int b = pair >> 5, j = pair & 31;
        const int K = k0 + j;
        float s = 0.f;
#pragma unroll
        for (int i = 0; i < 8; i++) s += g_p1[sub * 8 + i][b][K];
        s_pf[pair][sub] = s;
    }
    __syncthreads();
    if (tid < B_ * KCH_) {
        const int b = tid >> 5, j = tid & 31;
        s_in[b][j] = bv[k0 + j] + ((s_pf[tid][0] + s_pf[tid][1]) +
                                   (s_pf[tid][2] + s_pf[tid][3]));
    }
    __syncthreads();
    gemv_compute(tp, s_in, s_red, slab, tid, &g_p2[kc][0][0]);

    // Prefetch bp before the barrier.
    const int b  = bid >> 6;            // 0..3
    const int t0 = (bid & 63) * 16;
    float4 rbias = make_float4(0.f, 0.f, 0.f, 0.f);
    if (tid < 256) rbias = *(const float4*)&bp[tid * 4];
    grid_barrier(1);

    // ---- Phase C: fold 32 partials + bp (2-way parallel) ----
    {
        const int grp = tid >> 1;       // 0..255 c4-group
        const int sub = tid & 1;
        const int c4  = grp * 4;
        float4 s = make_float4(0.f, 0.f, 0.f, 0.f);
#pragma unroll
        for (int i = 0; i < 16; i++) {
            const float4 v = *(const float4*)&g_p2[sub * 16 + i][b][c4];
            s.x += v.x; s.y += v.y; s.z += v.z; s.w += v.w;
        }
        s_fold[tid] = s;
    }
    __syncthreads();
    if (tid < 256) {
        float4 r = rbias;
        const float4 v0 = s_fold[tid * 2];
        const float4 v1 = s_fold[tid * 2 + 1];
        r.x += v0.x + v1.x;
        r.y += v0.y + v1.y;
        r.z += v0.z + v1.z;
        r.w += v0.w + v1.w;
        *(float4*)&s_row[tid * 4] = r;
    }
    __syncthreads();

    // ---- TMA bulk broadcast: 16 rows of 4 KB (one lane per row) ----
    if (tid < 16) {
        asm volatile("fence.proxy.async.shared::cta;" ::: "memory");
        const uint32_t saddr = (uint32_t)__cvta_generic_to_shared(s_row);
        const float* dst = &out[(size_t)(b * T_ + t0 + tid) * C_];
        asm volatile(
            "cp.async.bulk.global.shared::cta.bulk_group [%0], [%1], %2;"
            :: "l"(dst), "r"(saddr), "r"(4096) : "memory");
        asm volatile("cp.async.bulk.commit_group;" ::: "memory");
        asm volatile("cp.async.bulk.wait_group 0;" ::: "memory");
    }
}

// Inputs: 0 x, 1 vf, 2 Wq, 3 bq, 4 Wk, 5 bk, 6 Wv, 7 bv, 8 Wp, 9 bp
extern "C" void kernel_launch(void* const* d_in, const int* in_sizes, int n_in,
                              void* d_out, int out_size) {
    const float* vf = (const float*)d_in[1];
    const float* Wv = (const float*)d_in[6];
    const float* bv = (const float*)d_in[7];
    const float* Wp = (const float*)d_in[8];
    const float* bp = (const float*)d_in[9];
    float* out = (float*)d_out;

    ca_fused<<<GRID_, BLOCK_>>>(vf, Wv, bv, Wp, bp, out);
}